// round 15
// baseline (speedup 1.0000x reference)
#include <cuda_runtime.h>
#include <cstdint>

#define T_C 4
#define N_C 20000
#define E_C 320000
#define FIN 12
#define EH 32
#define NH 64
#define GH 64

// ---------------- device scratch ----------------
__device__ __align__(16) float d_xenc[T_C * N_C * NH];
__device__ __align__(16) float d_xsA [T_C * N_C * NH];
__device__ __align__(16) float d_xsB [T_C * N_C * NH];
__device__ __align__(16) float d_nsx [T_C * N_C * NH];
__device__ __align__(16) float d_ndx [T_C * N_C * NH];
__device__ __align__(16) float d_nsf [N_C * NH];
__device__ __align__(16) float d_acc [N_C * NH];
__device__ __align__(16) float d_es0 [(size_t)T_C * E_C * EH];
__device__ __align__(16) float d_e1  [(size_t)E_C * EH];
__device__ float d_degw[N_C];
__device__ int   d_cnt_r[N_C];
__device__ int   d_ptr_r[N_C + 1];
__device__ int   d_cur_r[N_C];
__device__ int2  d_csr_r_es[E_C];
__device__ float d_g[GH], d_gsave[GH];
__device__ float d_gce[EH];
__device__ __align__(16) float d_gcn[NH];
__device__ float d_esum[EH], d_xsum[NH];
__device__ float d_Pp[EH], d_Pm[EH];
__device__ int   d_fast0;
__device__ int   d_ctr;

__device__ __forceinline__ float dot4(float4 v, float4 w) {
    return v.x * w.x + v.y * w.y + v.z * w.z + v.w * w.w;
}

// ---------------- encode (+ zero cnt_r/degw/ctr) ----------------
__global__ __launch_bounds__(256) void k_encode(const float* __restrict__ na,
                                                const float* __restrict__ W_ne,
                                                const float* __restrict__ b_ne,
                                                float* __restrict__ xenc) {
    __shared__ float sW[FIN * NH + NH];
    __shared__ float sna[4 * FIN];
    int tid = threadIdx.x;
    int z = blockIdx.x * 256 + tid;
    if (z < N_C) d_cnt_r[z] = 0;
    else if (z < 2 * N_C) d_degw[z - N_C] = 0.f;
    else if (z == 2 * N_C) d_ctr = 0;
    for (int i = tid; i < FIN * NH + NH; i += 256)
        sW[i] = (i < FIN * NH) ? W_ne[i] : b_ne[i - FIN * NH];
    int row0 = blockIdx.x * 4;
    if (tid < 4 * FIN) sna[tid] = na[row0 * FIN + tid];
    __syncthreads();
    int r = tid >> 6, j = tid & 63;
    float v = sW[FIN * NH + j];
#pragma unroll
    for (int k = 0; k < FIN; k++) v += sna[r * FIN + k] * sW[k * NH + j];
    xenc[(size_t)(row0 + r) * 64 + j] = fmaxf(v, 0.f);
}

// ---------------- recv CSR build ----------------
__global__ __launch_bounds__(256) void k_hist_r(const int* __restrict__ eidx,
                                                const float* __restrict__ spL) {
    int i = blockIdx.x * 256 + threadIdx.x;
    int r = eidx[E_C + i];
    atomicAdd(&d_cnt_r[r], 1);
    atomicAdd(&d_degw[r], spL[i]);
}

__global__ __launch_bounds__(256) void k_scan_r() {
    __shared__ int sp[256];
    const int SEG = 79;
    int tid = threadIdx.x;
    int base = tid * SEG;
    int s = 0;
    for (int i = 0; i < SEG; i++) {
        int idx = base + i;
        if (idx < N_C) s += d_cnt_r[idx];
    }
    sp[tid] = s;
    __syncthreads();
    for (int off = 1; off < 256; off <<= 1) {
        int v = (tid >= off) ? sp[tid - off] : 0;
        __syncthreads();
        sp[tid] += v;
        __syncthreads();
    }
    int run = (tid > 0) ? sp[tid - 1] : 0;
    for (int i = 0; i < SEG; i++) {
        int idx = base + i;
        if (idx < N_C) { d_ptr_r[idx] = run; d_cur_r[idx] = run; run += d_cnt_r[idx]; }
    }
    if (tid == 255) d_ptr_r[N_C] = E_C;
}

__global__ __launch_bounds__(256) void k_scatter_r(const int* __restrict__ eidx) {
    int i = blockIdx.x * 256 + threadIdx.x;
    int r = eidx[E_C + i];
    int p = atomicAdd(&d_cur_r[r], 1);
    d_csr_r_es[p] = make_int2(i, eidx[i]);
}

// ---------------- batched precompute: quad-major weights ----------------
template <bool RESID, bool DOPREP>
__global__ __launch_bounds__(256) void k_batch_pre(float* __restrict__ xall,
                                                   const float* __restrict__ xenc,
                                                   const float* __restrict__ W_eb,
                                                   const float* __restrict__ W_nb,
                                                   float* __restrict__ nsx,
                                                   float* __restrict__ ndx,
                                                   float* __restrict__ nsf,
                                                   float* __restrict__ accz,
                                                   const float* __restrict__ g0,
                                                   const float* __restrict__ b_eb,
                                                   const float* __restrict__ b_nb,
                                                   const float* __restrict__ W_ee,
                                                   const float* __restrict__ b_ee) {
    __shared__ float4 sW4[16 * 128];
    __shared__ float sv[32 * 68];
    int tid = threadIdx.x;
    if (blockIdx.x == 0) {
        if (DOPREP && tid < 32) {
            float pp = 0.f, pm = 0.f;
            bool ok = true;
#pragma unroll
            for (int k = 0; k < EH; k++) {
                float w = W_ee[k];
                pp += fmaxf(w, 0.f)  * W_eb[k * EH + tid];
                pm += fmaxf(-w, 0.f) * W_eb[k * EH + tid];
                if (b_ee[k] != 0.f) ok = false;
            }
            d_Pp[tid] = pp; d_Pm[tid] = pm;
            if (tid == 0) d_fast0 = ok ? 1 : 0;
        }
        if (tid >= 32 && tid < 64) {
            int j = tid - 32;
            float v = b_eb[j];
#pragma unroll
            for (int k = 0; k < GH; k++) v += g0[k] * W_eb[(320 + k) * EH + j];
            d_gce[j] = v;
        } else if (tid >= 64 && tid < 128) {
            int j = tid - 64;
            float v = b_nb[j];
#pragma unroll
            for (int k = 0; k < GH; k++) v += g0[k] * W_nb[(192 + k) * NH + j];
            d_gcn[j] = v;
        } else if (tid >= 128 && tid < 192) {
            d_g[tid - 128] = g0[tid - 128];
        }
    }
    for (int idx = tid; idx < 16 * 128; idx += 256) {
        int kq = idx >> 7, j = idx & 127;
        float4 w;
#pragma unroll
        for (int c = 0; c < 4; c++) {
            int k = 4 * kq + c;
            float wv = (j < 32) ? W_eb[(64 + k) * EH + j]
                     : (j < 64) ? W_eb[(192 + k) * EH + (j - 32)]
                                : W_nb[k * NH + (j - 64)];
            ((float*)&w)[c] = wv;
        }
        sW4[idx] = w;
    }
    int base = blockIdx.x * 32;
    for (int idx = tid; idx < 32 * 64; idx += 256) {
        int n = idx >> 6, c = idx & 63;
        size_t row = base + n;
        float v = xall[row * 64 + c];
        if (RESID) { v += xenc[row * 64 + c]; xall[row * 64 + c] = v; }
        sv[n * 68 + c] = v;
    }
    __syncthreads();
    bool donsf = (base < N_C);
    int og = tid & 31, ng = tid >> 5;
    float acc[16];
#pragma unroll
    for (int i = 0; i < 16; i++) acc[i] = 0.f;
#pragma unroll
    for (int kq = 0; kq < 16; kq++) {
        float4 v[4], w[4];
#pragma unroll
        for (int c = 0; c < 4; c++) v[c] = *(const float4*)&sv[(ng + 8 * c) * 68 + 4 * kq];
#pragma unroll
        for (int d = 0; d < 4; d++) w[d] = sW4[kq * 128 + og + 32 * d];
#pragma unroll
        for (int c = 0; c < 4; c++)
#pragma unroll
            for (int d = 0; d < 4; d++) acc[c * 4 + d] += dot4(v[c], w[d]);
    }
#pragma unroll
    for (int c = 0; c < 4; c++) {
        size_t row = base + ng + 8 * c;
#pragma unroll
        for (int d = 0; d < 4; d++) {
            int jp = og + 32 * d;
            if (d < 2) {
                nsx[row * 64 + jp] = acc[c * 4 + d];
                if (donsf) {
                    nsf[row * 64 + jp] = acc[c * 4 + d];
                    accz[row * 64 + jp] = 0.f;
                }
            } else {
                ndx[row * 64 + (jp - 64)] = acc[c * 4 + d];
            }
        }
    }
}

// ---------------- edge step: inline GEMV + scalar atomics; 4 blocks/SM ----------------
template <bool L0, bool HE, bool SUM, bool EOUT>
__global__ __launch_bounds__(256, 4) void k_edge10(const int* __restrict__ eidx,
                                                   const float* __restrict__ ea_t,
                                                   const float* __restrict__ ein,
                                                   const float* __restrict__ he,
                                                   float* __restrict__ eout,
                                                   const float* __restrict__ nsf,
                                                   float* __restrict__ accbuf,
                                                   const float* __restrict__ W_eb,
                                                   const float* __restrict__ W_ee,
                                                   const float* __restrict__ b_ee) {
    __shared__ float4 sWe[8 * 32];
    __shared__ float4 sWh[HE ? 8 * 32 : 1];
    __shared__ float  sv [64 * 36];
    __shared__ float  svh[HE ? 64 * 36 : 4];
    __shared__ int    sidx[128];
    __shared__ float  sa[L0 ? 64 : 1];
    __shared__ float  swee[L0 ? 32 : 1], sbee[L0 ? 32 : 1];
    __shared__ float  sred[256];
    int tid = threadIdx.x;
    int e0b = blockIdx.x * 64;
    int fast = L0 ? d_fast0 : 0;

    if (tid < 64) {
        sidx[tid]      = eidx[e0b + tid];
        sidx[64 + tid] = eidx[E_C + e0b + tid];
        if (L0) sa[tid] = ea_t[e0b + tid];
    }
    if (L0 && tid >= 64 && tid < 96) { swee[tid - 64] = W_ee[tid - 64]; sbee[tid - 64] = b_ee[tid - 64]; }
    if (tid < 256) {
        int q = tid >> 5, j = tid & 31;
        float4 w;
        w.x = W_eb[(4 * q + 0) * EH + j];
        w.y = W_eb[(4 * q + 1) * EH + j];
        w.z = W_eb[(4 * q + 2) * EH + j];
        w.w = W_eb[(4 * q + 3) * EH + j];
        sWe[q * 32 + j] = w;
        if (HE) {
            float4 w2;
            w2.x = W_eb[(32 + 4 * q + 0) * EH + j];
            w2.y = W_eb[(32 + 4 * q + 1) * EH + j];
            w2.z = W_eb[(32 + 4 * q + 2) * EH + j];
            w2.w = W_eb[(32 + 4 * q + 3) * EH + j];
            sWh[q * 32 + j] = w2;
        }
    }
    if (!L0) {
        const float4* p = (const float4*)(ein + (size_t)e0b * 32);
        for (int idx = tid; idx < 64 * 8; idx += 256) {
            int e = idx >> 3, q = idx & 7;
            *(float4*)&sv[e * 36 + 4 * q] = p[idx];
        }
    }
    if (HE) {
        const float4* p = (const float4*)(he + (size_t)e0b * 32);
        for (int idx = tid; idx < 64 * 8; idx += 256) {
            int e = idx >> 3, q = idx & 7;
            *(float4*)&svh[e * 36 + 4 * q] = p[idx];
        }
    }
    __syncthreads();
    if (L0 && !fast) {
        for (int idx = tid; idx < 64 * 32; idx += 256) {
            int e = idx >> 5, k = idx & 31;
            sv[e * 36 + k] = fmaxf(sa[e] * swee[k] + sbee[k], 0.f);
        }
    }
    if (L0) __syncthreads();

    int lane = tid & 31, wid = tid >> 5;
    float gce = d_gce[lane];
    float pp = 0.f, pm = 0.f;
    if (L0) { pp = d_Pp[lane]; pm = d_Pm[lane]; }
    float esum = 0.f;
#pragma unroll
    for (int i = 0; i < 8; i++) {
        int el = wid * 8 + i;
        size_t e = e0b + el;
        int s = sidx[el], r = sidx[64 + el];
        float b = gce;
        if (L0 && fast) {
            float a = sa[el];
            b += (a >= 0.f) ? a * pp : -a * pm;
        } else {
#pragma unroll
            for (int q = 0; q < 8; q++)
                b += dot4(*(const float4*)&sv[el * 36 + 4 * q], sWe[q * 32 + lane]);
        }
        if (HE) {
#pragma unroll
            for (int q = 0; q < 8; q++)
                b += dot4(*(const float4*)&svh[el * 36 + 4 * q], sWh[q * 32 + lane]);
        }
        b += nsf[(size_t)s * 64 + lane] + nsf[(size_t)r * 64 + 32 + lane];
        float en = fmaxf(b, 0.f);
        if (EOUT) eout[e * 32 + lane] = en;
        atomicAdd(&accbuf[(size_t)s * 64 + lane], en);
        atomicAdd(&accbuf[(size_t)r * 64 + 32 + lane], en);
        if (SUM) esum += en;
    }
    if (SUM) {
        sred[tid] = esum;
        __syncthreads();
        if (wid == 0) {
            float s2 = 0.f;
#pragma unroll
            for (int w = 0; w < 8; w++) s2 += sred[w * 32 + lane];
            atomicAdd(&d_esum[lane], s2);
        }
    }
}

// ---------------- fused node step: 16 nodes/block (grid 1250), vectorized epilogue ----------------
// smem floats: [0..KQ*256) weights; sx = sm+4096 (16*68); sv = sm+(HASH?8192:4096) stride KW.
template <bool HASH, bool TD, bool SD, bool NSH, bool GLOB>
__global__ __launch_bounds__(256) void k_node15(
    const float* __restrict__ ndx_t, const float* __restrict__ hx,
    const float* __restrict__ accb, const float* __restrict__ W_nb,
    float* __restrict__ xsout, float* __restrict__ tdout, float* __restrict__ sdout,
    const float* __restrict__ degw, const float* __restrict__ coeff,
    const float* __restrict__ nsx1, const float* __restrict__ W_eb,
    float* __restrict__ nsf, float* __restrict__ accz,
    const float* __restrict__ W_gb, const float* __restrict__ b_gb,
    const float* __restrict__ b_eb, const float* __restrict__ b_nb,
    int save) {
    constexpr int KW = HASH ? 132 : 68;
    constexpr int KQ = HASH ? 32 : 16;
    extern __shared__ float sm[];
    float4* sW4 = (float4*)sm;
    float*  sx  = sm + 4096;
    float*  sv  = sm + (HASH ? 8192 : 4096);
    float4* nW4 = (float4*)sm;
    __shared__ int slast;
    int tid = threadIdx.x;
    int base = blockIdx.x * 16;
    for (int idx = tid; idx < KQ * 64; idx += 256) {
        int kq = idx >> 6, j = idx & 63;
        int r0 = (HASH ? 64 : 128) + 4 * kq;
        float4 w;
        w.x = W_nb[(r0 + 0) * NH + j];
        w.y = W_nb[(r0 + 1) * NH + j];
        w.z = W_nb[(r0 + 2) * NH + j];
        w.w = W_nb[(r0 + 3) * NH + j];
        sW4[idx] = w;
    }
    const float4* h4 = (const float4*)hx;
    const float4* a4 = (const float4*)accb;
    for (int idx = tid; idx < 16 * (HASH ? 32 : 16); idx += 256) {
        int n, q;
        if (HASH) { n = idx >> 5; q = idx & 31; }
        else      { n = idx >> 4; q = idx & 15; }
        float4 v;
        if (HASH) v = (q < 16) ? h4[(size_t)(base + n) * 16 + q]
                               : a4[(size_t)(base + n) * 16 + q - 16];
        else      v = a4[(size_t)(base + n) * 16 + q];
        *(float4*)&sv[n * KW + 4 * q] = v;
    }
    __syncthreads();
    int og = tid & 15, ng = tid >> 4;   // 16 nodes, 1 per thread-group row
    float acc[4];
#pragma unroll
    for (int i = 0; i < 4; i++) acc[i] = 0.f;
#pragma unroll 8
    for (int kq = 0; kq < KQ; kq++) {
        float4 v = *(const float4*)&sv[ng * KW + 4 * kq];
        float4 w[4];
#pragma unroll
        for (int d = 0; d < 4; d++) w[d] = sW4[kq * 64 + og + 16 * d];
#pragma unroll
        for (int d = 0; d < 4; d++) acc[d] += dot4(v, w[d]);
    }
    __syncthreads();   // GEMM reads done; safe to overwrite sx / weight region
#pragma unroll
    for (int d = 0; d < 4; d++)
        sx[ng * 68 + og + 16 * d] = acc[d];
    if (NSH) {
        for (int idx = tid; idx < 16 * 64; idx += 256) {
            int kq = idx >> 6, j = idx & 63;
            int b0 = (j < 32) ? 128 : 256;
            int jj = j & 31;
            float4 w;
            w.x = W_eb[(b0 + 4 * kq + 0) * EH + jj];
            w.y = W_eb[(b0 + 4 * kq + 1) * EH + jj];
            w.z = W_eb[(b0 + 4 * kq + 2) * EH + jj];
            w.w = W_eb[(b0 + 4 * kq + 3) * EH + jj];
            nW4[idx] = w;
        }
    }
    __syncthreads();
    // vectorized epilogue: thread -> (node n = tid>>4, quad q = tid&15)
    float cw = SD ? coeff[0] : 0.f;
    {
        int n = tid >> 4, q = tid & 15;
        size_t row = base + n;
        float4 a = *(const float4*)&sx[n * 68 + 4 * q];
        float4 nd = ((const float4*)ndx_t)[row * 16 + q];
        float4 g = *(const float4*)&d_gcn[4 * q];
        float4 x;
        x.x = fmaxf(a.x + nd.x + g.x, 0.f);
        x.y = fmaxf(a.y + nd.y + g.y, 0.f);
        x.z = fmaxf(a.z + nd.z + g.z, 0.f);
        x.w = fmaxf(a.w + nd.w + g.w, 0.f);
        *(float4*)&sx[n * 68 + 4 * q] = x;
        ((float4*)xsout)[row * 16 + q] = x;
        if (TD) {
            float4 t = x;
            if (HASH) {
                float4 h = h4[row * 16 + q];
                t.x -= h.x; t.y -= h.y; t.z -= h.z; t.w -= h.w;
            }
            ((float4*)tdout)[row * 16 + q] = t;
        }
        if (SD) {
            float dgv = -cw * degw[row];
            ((float4*)sdout)[row * 16 + q] =
                make_float4(dgv * x.x, dgv * x.y, dgv * x.z, dgv * x.w);
        }
        if (NSH) ((float4*)accz)[row * 16 + q] = make_float4(0.f, 0.f, 0.f, 0.f);
    }
    if (NSH || GLOB) __syncthreads();
    if (GLOB && tid < 64) {
        float s = 0.f;
#pragma unroll
        for (int n = 0; n < 16; n++) s += sx[n * 68 + tid];
        atomicAdd(&d_xsum[tid], s);
    }
    if (NSH) {
        float a2[4];
#pragma unroll
        for (int i = 0; i < 4; i++) a2[i] = 0.f;
#pragma unroll
        for (int kq = 0; kq < 16; kq++) {
            float4 v = *(const float4*)&sx[ng * 68 + 4 * kq];
            float4 w[4];
#pragma unroll
            for (int d = 0; d < 4; d++) w[d] = nW4[kq * 64 + og + 16 * d];
#pragma unroll
            for (int d = 0; d < 4; d++) a2[d] += dot4(v, w[d]);
        }
        size_t row = base + ng;
#pragma unroll
        for (int d = 0; d < 4; d++) {
            int j = og + 16 * d;
            nsf[row * 64 + j] = a2[d] + nsx1[row * 64 + j];
        }
    }
    if (GLOB) {
        __syncthreads();
        __threadfence();
        if (tid == 0) slast = (atomicAdd(&d_ctr, 1) == (int)gridDim.x - 1);
        __syncthreads();
        if (slast) {
            float* gcat = sx;
            float* gnew = sx + 160;
            if (tid < 64) gcat[tid] = d_xsum[tid] * (1.0f / N_C);
            else if (tid < 96) gcat[tid] = d_esum[tid - 64] * (1.0f / E_C);
            else if (tid < 160) gcat[tid] = d_g[tid - 96];
            __syncthreads();
            if (tid < GH) {
                float v = b_gb[tid];
                for (int k = 0; k < 160; k++) v += gcat[k] * W_gb[k * GH + tid];
                gnew[tid] = fmaxf(v, 0.f);
            }
            __syncthreads();
            if (tid < GH) {
                d_g[tid] = gnew[tid];
                if (save) d_gsave[tid] = gnew[tid];
                d_xsum[tid] = 0.f;
            }
            if (tid < EH) {
                d_esum[tid] = 0.f;
                float v = b_eb[tid];
#pragma unroll
                for (int k = 0; k < GH; k++) v += gnew[k] * W_eb[(320 + k) * EH + tid];
                d_gce[tid] = v;
            } else if (tid < 32 + NH) {
                int j = tid - 32;
                float v = b_nb[j];
#pragma unroll
                for (int k = 0; k < GH; k++) v += gnew[k] * W_nb[(192 + k) * NH + j];
                d_gcn[j] = v;
            }
            if (tid == 0) d_ctr = 0;
        }
    }
}

// ---------------- node-parallel sder over recv-CSR (all 4 steps) ----------------
__global__ __launch_bounds__(256) void k_sder8(const int* __restrict__ pr,
                                               const int2* __restrict__ pre,
                                               const float* __restrict__ spL,
                                               const float* __restrict__ coeff,
                                               const float* __restrict__ xsB,
                                               float* __restrict__ sd_out) {
    int lane = threadIdx.x & 31, wid = threadIdx.x >> 5;
    int n = blockIdx.x * 8 + wid;
    int p0 = pr[n], p1 = pr[n + 1];
    float a[8] = {0.f, 0.f, 0.f, 0.f, 0.f, 0.f, 0.f, 0.f};
    for (int i = p0; i < p1; i++) {
        int2 es = pre[i];
        float w = spL[es.x];
        const float* xr = xsB + (size_t)es.y * 64;
#pragma unroll
        for (int t = 0; t < 4; t++) {
            a[t * 2]     += w * xr[(size_t)t * N_C * 64 + lane];
            a[t * 2 + 1] += w * xr[(size_t)t * N_C * 64 + 32 + lane];
        }
    }
    float cw = coeff[0];
#pragma unroll
    for (int t = 0; t < 4; t++) {
        size_t o = (size_t)t * N_C * 64 + (size_t)n * 64;
        sd_out[o + lane]      += cw * a[t * 2];
        sd_out[o + 32 + lane] += cw * a[t * 2 + 1];
    }
}

// ---------------- decode: quad-major weights ----------------
__global__ __launch_bounds__(256) void k_decode13(const float* __restrict__ xa,
                                                  const float* __restrict__ xb,
                                                  const float* __restrict__ W1,
                                                  const float* __restrict__ b1,
                                                  const float* __restrict__ W2,
                                                  const float* __restrict__ b2,
                                                  float* __restrict__ outn) {
    __shared__ float4 sW4[16 * 64];
    __shared__ float sv[64 * 68];
    __shared__ float sw2[NH];
    int tid = threadIdx.x;
    int base = blockIdx.x * 64;
    for (int idx = tid; idx < 16 * 64; idx += 256) {
        int kq = idx >> 6, j = idx & 63;
        float4 w;
        w.x = W1[(4 * kq + 0) * NH + j];
        w.y = W1[(4 * kq + 1) * NH + j];
        w.z = W1[(4 * kq + 2) * NH + j];
        w.w = W1[(4 * kq + 3) * NH + j];
        sW4[idx] = w;
    }
    const float4* a4 = (const float4*)xa;
    const float4* b4 = (const float4*)xb;
    for (int idx = tid; idx < 64 * 16; idx += 256) {
        int n = idx >> 4, q = idx & 15;
        float4 va = a4[(size_t)(base + n) * 16 + q];
        float4 vb = b4[(size_t)(base + n) * 16 + q];
        va.x += vb.x; va.y += vb.y; va.z += vb.z; va.w += vb.w;
        *(float4*)&sv[n * 68 + 4 * q] = va;
    }
    if (tid < NH) sw2[tid] = W2[tid];
    __syncthreads();
    int og = tid & 15, ng = tid >> 4;
    float acc[16];
#pragma unroll
    for (int i = 0; i < 16; i++) acc[i] = 0.f;
#pragma unroll
    for (int kq = 0; kq < 16; kq++) {
        float4 v[4], w[4];
#pragma unroll
        for (int c = 0; c < 4; c++) v[c] = *(const float4*)&sv[(ng + 16 * c) * 68 + 4 * kq];
#pragma unroll
        for (int d = 0; d < 4; d++) w[d] = sW4[kq * 64 + og + 16 * d];
#pragma unroll
        for (int c = 0; c < 4; c++)
#pragma unroll
            for (int d = 0; d < 4; d++) acc[c * 4 + d] += dot4(v[c], w[d]);
    }
    float w2[4], bb[4];
#pragma unroll
    for (int d = 0; d < 4; d++) { w2[d] = sw2[og + 16 * d]; bb[d] = b1[og + 16 * d]; }
    float b20 = b2[0];
#pragma unroll
    for (int c = 0; c < 4; c++) {
        float p = 0.f;
#pragma unroll
        for (int d = 0; d < 4; d++) p += fmaxf(acc[c * 4 + d] + bb[d], 0.f) * w2[d];
        p += __shfl_down_sync(0xffffffffu, p, 8);
        p += __shfl_down_sync(0xffffffffu, p, 4);
        p += __shfl_down_sync(0xffffffffu, p, 2);
        p += __shfl_down_sync(0xffffffffu, p, 1);
        if (og == 0) outn[base + ng + 16 * c] = p + b20;
    }
}

// ---------------- host launcher ----------------
extern "C" void kernel_launch(void* const* d_in, const int* in_sizes, int n_in,
                              void* d_out, int out_size) {
    const float* node_attr  = (const float*)d_in[0];
    const float* edge_attr  = (const float*)d_in[1];
    const int*   edge_index = (const int*)  d_in[2];
    const float* spL        = (const float*)d_in[3];
    const float* gattr      = (const float*)d_in[4];
    const float* coeff      = (const float*)d_in[5];
    const float* W_ee = (const float*)d_in[6];
    const float* b_ee = (const float*)d_in[7];
    const float* W_ne = (const float*)d_in[8];
    const float* b_ne = (const float*)d_in[9];
    const float* W_eb = (const float*)d_in[10];
    const float* b_eb = (const float*)d_in[11];
    const float* W_nb = (const float*)d_in[12];
    const float* b_nb = (const float*)d_in[13];
    const float* W_gb = (const float*)d_in[14];
    const float* b_gb = (const float*)d_in[15];
    const float* W_nd1 = (const float*)d_in[16];
    const float* b_nd1 = (const float*)d_in[17];
    const float* W_nd2 = (const float*)d_in[18];
    const float* b_nd2 = (const float*)d_in[19];

    float* out    = (float*)d_out;
    float* out_td = out + (size_t)T_C * N_C;
    float* out_sd = out_td + (size_t)T_C * N_C * NH;

    float *xenc, *xsA, *xsB, *nsx, *ndx, *nsf, *acc, *es0, *e1;
    float *degw, *gsave;
    int *ptr_r;
    int2 *csr_r_es;
    cudaGetSymbolAddress((void**)&xenc, d_xenc);
    cudaGetSymbolAddress((void**)&xsA,  d_xsA);
    cudaGetSymbolAddress((void**)&xsB,  d_xsB);
    cudaGetSymbolAddress((void**)&nsx,  d_nsx);
    cudaGetSymbolAddress((void**)&ndx,  d_ndx);
    cudaGetSymbolAddress((void**)&nsf,  d_nsf);
    cudaGetSymbolAddress((void**)&acc,  d_acc);
    cudaGetSymbolAddress((void**)&es0,  d_es0);
    cudaGetSymbolAddress((void**)&e1,   d_e1);
    cudaGetSymbolAddress((void**)&degw, d_degw);
    cudaGetSymbolAddress((void**)&gsave, d_gsave);
    cudaGetSymbolAddress((void**)&ptr_r, d_ptr_r);
    cudaGetSymbolAddress((void**)&csr_r_es, d_csr_r_es);

    const int SM_H = (8192 + 16 * 132) * 4;   // 41216
    const int SM_L = (4096 + 16 * 68) * 4;    // 20736
    cudaFuncSetAttribute(k_node15<false, false, false, true,  true >, cudaFuncAttributeMaxDynamicSharedMemorySize, SM_L);
    cudaFuncSetAttribute(k_node15<true,  false, false, true,  true >, cudaFuncAttributeMaxDynamicSharedMemorySize, SM_H);
    cudaFuncSetAttribute(k_node15<true,  false, false, false, false>, cudaFuncAttributeMaxDynamicSharedMemorySize, SM_H);
    cudaFuncSetAttribute(k_node15<false, true,  true,  true,  true >, cudaFuncAttributeMaxDynamicSharedMemorySize, SM_L);
    cudaFuncSetAttribute(k_node15<true,  true,  true,  true,  true >, cudaFuncAttributeMaxDynamicSharedMemorySize, SM_H);
    cudaFuncSetAttribute(k_node15<true,  true,  true,  false, false>, cudaFuncAttributeMaxDynamicSharedMemorySize, SM_H);

    const int EGRID = E_C / 64;      // 5000
    const int NGRID = N_C / 16;      // 1250
    const size_t NSZ = (size_t)N_C * NH;
    const size_t ESZ = (size_t)E_C * EH;

    // 1. encode (zeros CSR counters / degw / ctr)
    k_encode<<<(T_C * N_C) / 4, 256>>>(node_attr, W_ne, b_ne, xenc);
    // 2. batch_pre L0 (+prep, +ginit from gattr, +nsf/acc init)
    k_batch_pre<false, true><<<(T_C * N_C) / 32, 256>>>(xenc, nullptr, W_eb, W_nb,
        nsx, ndx, nsf, acc, gattr, b_eb, b_nb, W_ee, b_ee);
    // 3. L0 edge t=0
    k_edge10<true, false, true, true><<<EGRID, 256>>>(edge_index, edge_attr, nullptr, nullptr,
        es0, nsf, acc, W_eb, W_ee, b_ee);
    // 4. L0 node t=0  <-- ncu capture window
    k_node15<false, false, false, true, true><<<NGRID, 256, SM_L>>>(
        ndx, nullptr, acc, W_nb, xsA, nullptr, nullptr, nullptr, nullptr,
        nsx + NSZ, W_eb, nsf, acc, W_gb, b_gb, b_eb, b_nb, 1);
    // 5-7. recv CSR build (needed only by sder at the end)
    k_hist_r<<<E_C / 256, 256>>>(edge_index, spL);
    k_scan_r<<<1, 256>>>();
    k_scatter_r<<<E_C / 256, 256>>>(edge_index);

    // ================= layer 0, t=1..3 =================
    for (int t = 1; t < T_C; t++) {
        const float* ea_t = edge_attr + (size_t)t * E_C;
        float* es_t = es0 + (size_t)t * ESZ;
        if (t < 3)
            k_edge10<true, true, true, true><<<EGRID, 256>>>(edge_index, ea_t, nullptr,
                es0 + (size_t)(t - 1) * ESZ, es_t, nsf, acc, W_eb, W_ee, b_ee);
        else
            k_edge10<true, true, false, true><<<EGRID, 256>>>(edge_index, ea_t, nullptr,
                es0 + (size_t)(t - 1) * ESZ, es_t, nsf, acc, W_eb, W_ee, b_ee);
        float* xs_t = xsA + (size_t)t * NSZ;
        const float* nsx1 = nsx + (size_t)(t + 1) * NSZ;
        if (t < 3)
            k_node15<true, false, false, true, true><<<NGRID, 256, SM_H>>>(
                ndx + (size_t)t * NSZ, xsA + (size_t)(t - 1) * NSZ, acc, W_nb, xs_t, nullptr, nullptr, nullptr, nullptr,
                nsx1, W_eb, nsf, acc, W_gb, b_gb, b_eb, b_nb, 0);
        else
            k_node15<true, false, false, false, false><<<NGRID, 256, SM_H>>>(
                ndx + (size_t)t * NSZ, xsA + (size_t)(t - 1) * NSZ, acc, W_nb, xs_t, nullptr, nullptr, nullptr, nullptr,
                nullptr, W_eb, nsf, acc, W_gb, b_gb, b_eb, b_nb, 0);
    }

    // ================= layer 1 =================
    k_batch_pre<true, false><<<(T_C * N_C) / 32, 256>>>(xsA, xenc, W_eb, W_nb,
        nsx, ndx, nsf, acc, gsave, b_eb, b_nb, W_ee, b_ee);
    for (int t = 0; t < T_C; t++) {
        const float* es_t = es0 + (size_t)t * ESZ;
        if (t == 0)
            k_edge10<false, false, true, true><<<EGRID, 256>>>(edge_index, nullptr, es_t,
                nullptr, e1, nsf, acc, W_eb, W_ee, b_ee);
        else if (t < 3)
            k_edge10<false, true, true, true><<<EGRID, 256>>>(edge_index, nullptr, es_t,
                e1, e1, nsf, acc, W_eb, W_ee, b_ee);
        else
            k_edge10<false, true, false, false><<<EGRID, 256>>>(edge_index, nullptr, es_t,
                e1, e1, nsf, acc, W_eb, W_ee, b_ee);
        float* xs_t = xsB + (size_t)t * NSZ;
        float* td_t = out_td + (size_t)t * NSZ;
        float* sd_t = out_sd + (size_t)t * NSZ;
        const float* nsx1 = nsx + (size_t)(t + 1) * NSZ;
        if (t == 0)
            k_node15<false, true, true, true, true><<<NGRID, 256, SM_L>>>(
                ndx + (size_t)t * NSZ, nullptr, acc, W_nb, xs_t, td_t, sd_t, degw, coeff,
                nsx1, W_eb, nsf, acc, W_gb, b_gb, b_eb, b_nb, 0);
        else if (t < 3)
            k_node15<true, true, true, true, true><<<NGRID, 256, SM_H>>>(
                ndx + (size_t)t * NSZ, xsB + (size_t)(t - 1) * NSZ, acc, W_nb, xs_t, td_t, sd_t, degw, coeff,
                nsx1, W_eb, nsf, acc, W_gb, b_gb, b_eb, b_nb, 0);
        else
            k_node15<true, true, true, false, false><<<NGRID, 256, SM_H>>>(
                ndx + (size_t)t * NSZ, xsB + (size_t)(t - 1) * NSZ, acc, W_nb, xs_t, td_t, sd_t, degw, coeff,
                nullptr, W_eb, nsf, acc, W_gb, b_gb, b_eb, b_nb, 0);
    }

    k_sder8<<<N_C / 8, 256>>>(ptr_r, csr_r_es, spL, coeff, xsB, out_sd);
    k_decode13<<<(T_C * N_C) / 64, 256>>>(xsA, xsB, W_nd1, b_nd1, W_nd2, b_nd2, out);
}

// round 16
// speedup vs baseline: 1.1213x; 1.1213x over previous
#include <cuda_runtime.h>
#include <cstdint>

#define T_C 4
#define N_C 20000
#define E_C 320000
#define FIN 12
#define EH 32
#define NH 64
#define GH 64

// ---------------- device scratch ----------------
__device__ __align__(16) float d_xenc[T_C * N_C * NH];
__device__ __align__(16) float d_xsA [T_C * N_C * NH];
__device__ __align__(16) float d_xsB [T_C * N_C * NH];
__device__ __align__(16) float d_nsx [T_C * N_C * NH];
__device__ __align__(16) float d_ndx [T_C * N_C * NH];
__device__ __align__(16) float d_nsf [N_C * NH];
__device__ __align__(16) float d_acc [N_C * NH];
__device__ __align__(16) float d_es0 [(size_t)T_C * E_C * EH];
__device__ __align__(16) float d_e1  [(size_t)E_C * EH];
__device__ float d_degw[N_C];
__device__ int   d_cnt_r[N_C];
__device__ int   d_ptr_r[N_C + 1];
__device__ int   d_cur_r[N_C];
__device__ int2  d_csr_r_es[E_C];
__device__ float d_g[GH], d_gsave[GH];
__device__ float d_gce[EH];
__device__ __align__(16) float d_gcn[NH];
__device__ float d_esum[EH], d_xsum[NH];
__device__ float d_Pp[EH], d_Pm[EH];
__device__ int   d_fast0;
__device__ int   d_ctr;

__device__ __forceinline__ float dot4(float4 v, float4 w) {
    return v.x * w.x + v.y * w.y + v.z * w.z + v.w * w.w;
}

// ---------------- encode (+ zero cnt_r/degw/ctr) ----------------
__global__ __launch_bounds__(256) void k_encode(const float* __restrict__ na,
                                                const float* __restrict__ W_ne,
                                                const float* __restrict__ b_ne,
                                                float* __restrict__ xenc) {
    __shared__ float sW[FIN * NH + NH];
    __shared__ float sna[4 * FIN];
    int tid = threadIdx.x;
    int z = blockIdx.x * 256 + tid;
    if (z < N_C) d_cnt_r[z] = 0;
    else if (z < 2 * N_C) d_degw[z - N_C] = 0.f;
    else if (z == 2 * N_C) d_ctr = 0;
    for (int i = tid; i < FIN * NH + NH; i += 256)
        sW[i] = (i < FIN * NH) ? W_ne[i] : b_ne[i - FIN * NH];
    int row0 = blockIdx.x * 4;
    if (tid < 4 * FIN) sna[tid] = na[row0 * FIN + tid];
    __syncthreads();
    int r = tid >> 6, j = tid & 63;
    float v = sW[FIN * NH + j];
#pragma unroll
    for (int k = 0; k < FIN; k++) v += sna[r * FIN + k] * sW[k * NH + j];
    xenc[(size_t)(row0 + r) * 64 + j] = fmaxf(v, 0.f);
}

// ---------------- recv CSR build ----------------
__global__ __launch_bounds__(256) void k_hist_r(const int* __restrict__ eidx,
                                                const float* __restrict__ spL) {
    int i = blockIdx.x * 256 + threadIdx.x;
    int r = eidx[E_C + i];
    atomicAdd(&d_cnt_r[r], 1);
    atomicAdd(&d_degw[r], spL[i]);
}

__global__ __launch_bounds__(256) void k_scan_r() {
    __shared__ int sp[256];
    const int SEG = 79;
    int tid = threadIdx.x;
    int base = tid * SEG;
    int s = 0;
    for (int i = 0; i < SEG; i++) {
        int idx = base + i;
        if (idx < N_C) s += d_cnt_r[idx];
    }
    sp[tid] = s;
    __syncthreads();
    for (int off = 1; off < 256; off <<= 1) {
        int v = (tid >= off) ? sp[tid - off] : 0;
        __syncthreads();
        sp[tid] += v;
        __syncthreads();
    }
    int run = (tid > 0) ? sp[tid - 1] : 0;
    for (int i = 0; i < SEG; i++) {
        int idx = base + i;
        if (idx < N_C) { d_ptr_r[idx] = run; d_cur_r[idx] = run; run += d_cnt_r[idx]; }
    }
    if (tid == 255) d_ptr_r[N_C] = E_C;
}

__global__ __launch_bounds__(256) void k_scatter_r(const int* __restrict__ eidx) {
    int i = blockIdx.x * 256 + threadIdx.x;
    int r = eidx[E_C + i];
    int p = atomicAdd(&d_cur_r[r], 1);
    d_csr_r_es[p] = make_int2(i, eidx[i]);
}

// ---------------- batched precompute: quad-major weights ----------------
template <bool RESID, bool DOPREP>
__global__ __launch_bounds__(256) void k_batch_pre(float* __restrict__ xall,
                                                   const float* __restrict__ xenc,
                                                   const float* __restrict__ W_eb,
                                                   const float* __restrict__ W_nb,
                                                   float* __restrict__ nsx,
                                                   float* __restrict__ ndx,
                                                   float* __restrict__ nsf,
                                                   float* __restrict__ accz,
                                                   const float* __restrict__ g0,
                                                   const float* __restrict__ b_eb,
                                                   const float* __restrict__ b_nb,
                                                   const float* __restrict__ W_ee,
                                                   const float* __restrict__ b_ee) {
    __shared__ float4 sW4[16 * 128];
    __shared__ float sv[32 * 68];
    int tid = threadIdx.x;
    if (blockIdx.x == 0) {
        if (DOPREP && tid < 32) {
            float pp = 0.f, pm = 0.f;
            bool ok = true;
#pragma unroll
            for (int k = 0; k < EH; k++) {
                float w = W_ee[k];
                pp += fmaxf(w, 0.f)  * W_eb[k * EH + tid];
                pm += fmaxf(-w, 0.f) * W_eb[k * EH + tid];
                if (b_ee[k] != 0.f) ok = false;
            }
            d_Pp[tid] = pp; d_Pm[tid] = pm;
            if (tid == 0) d_fast0 = ok ? 1 : 0;
        }
        if (tid >= 32 && tid < 64) {
            int j = tid - 32;
            float v = b_eb[j];
#pragma unroll
            for (int k = 0; k < GH; k++) v += g0[k] * W_eb[(320 + k) * EH + j];
            d_gce[j] = v;
        } else if (tid >= 64 && tid < 128) {
            int j = tid - 64;
            float v = b_nb[j];
#pragma unroll
            for (int k = 0; k < GH; k++) v += g0[k] * W_nb[(192 + k) * NH + j];
            d_gcn[j] = v;
        } else if (tid >= 128 && tid < 192) {
            d_g[tid - 128] = g0[tid - 128];
        }
    }
    for (int idx = tid; idx < 16 * 128; idx += 256) {
        int kq = idx >> 7, j = idx & 127;
        float4 w;
#pragma unroll
        for (int c = 0; c < 4; c++) {
            int k = 4 * kq + c;
            float wv = (j < 32) ? W_eb[(64 + k) * EH + j]
                     : (j < 64) ? W_eb[(192 + k) * EH + (j - 32)]
                                : W_nb[k * NH + (j - 64)];
            ((float*)&w)[c] = wv;
        }
        sW4[idx] = w;
    }
    int base = blockIdx.x * 32;
    for (int idx = tid; idx < 32 * 64; idx += 256) {
        int n = idx >> 6, c = idx & 63;
        size_t row = base + n;
        float v = xall[row * 64 + c];
        if (RESID) { v += xenc[row * 64 + c]; xall[row * 64 + c] = v; }
        sv[n * 68 + c] = v;
    }
    __syncthreads();
    bool donsf = (base < N_C);
    int og = tid & 31, ng = tid >> 5;
    float acc[16];
#pragma unroll
    for (int i = 0; i < 16; i++) acc[i] = 0.f;
#pragma unroll
    for (int kq = 0; kq < 16; kq++) {
        float4 v[4], w[4];
#pragma unroll
        for (int c = 0; c < 4; c++) v[c] = *(const float4*)&sv[(ng + 8 * c) * 68 + 4 * kq];
#pragma unroll
        for (int d = 0; d < 4; d++) w[d] = sW4[kq * 128 + og + 32 * d];
#pragma unroll
        for (int c = 0; c < 4; c++)
#pragma unroll
            for (int d = 0; d < 4; d++) acc[c * 4 + d] += dot4(v[c], w[d]);
    }
#pragma unroll
    for (int c = 0; c < 4; c++) {
        size_t row = base + ng + 8 * c;
#pragma unroll
        for (int d = 0; d < 4; d++) {
            int jp = og + 32 * d;
            if (d < 2) {
                nsx[row * 64 + jp] = acc[c * 4 + d];
                if (donsf) {
                    nsf[row * 64 + jp] = acc[c * 4 + d];
                    accz[row * 64 + jp] = 0.f;
                }
            } else {
                ndx[row * 64 + (jp - 64)] = acc[c * 4 + d];
            }
        }
    }
}

// ---------------- edge step (r10): inline GEMV + scalar atomics; optional eout skip ----------------
template <bool L0, bool HE, bool SUM, bool EOUT>
__global__ __launch_bounds__(256) void k_edge10(const int* __restrict__ eidx,
                                                const float* __restrict__ ea_t,
                                                const float* __restrict__ ein,
                                                const float* __restrict__ he,
                                                float* __restrict__ eout,
                                                const float* __restrict__ nsf,
                                                float* __restrict__ accbuf,
                                                const float* __restrict__ W_eb,
                                                const float* __restrict__ W_ee,
                                                const float* __restrict__ b_ee) {
    __shared__ float4 sWe[8 * 32];
    __shared__ float4 sWh[HE ? 8 * 32 : 1];
    __shared__ float  sv [64 * 36];
    __shared__ float  svh[HE ? 64 * 36 : 4];
    __shared__ int    sidx[128];
    __shared__ float  sa[L0 ? 64 : 1];
    __shared__ float  swee[L0 ? 32 : 1], sbee[L0 ? 32 : 1];
    __shared__ float  sred[256];
    int tid = threadIdx.x;
    int e0b = blockIdx.x * 64;
    int fast = L0 ? d_fast0 : 0;

    if (tid < 64) {
        sidx[tid]      = eidx[e0b + tid];
        sidx[64 + tid] = eidx[E_C + e0b + tid];
        if (L0) sa[tid] = ea_t[e0b + tid];
    }
    if (L0 && tid >= 64 && tid < 96) { swee[tid - 64] = W_ee[tid - 64]; sbee[tid - 64] = b_ee[tid - 64]; }
    if (tid < 256) {
        int q = tid >> 5, j = tid & 31;
        float4 w;
        w.x = W_eb[(4 * q + 0) * EH + j];
        w.y = W_eb[(4 * q + 1) * EH + j];
        w.z = W_eb[(4 * q + 2) * EH + j];
        w.w = W_eb[(4 * q + 3) * EH + j];
        sWe[q * 32 + j] = w;
        if (HE) {
            float4 w2;
            w2.x = W_eb[(32 + 4 * q + 0) * EH + j];
            w2.y = W_eb[(32 + 4 * q + 1) * EH + j];
            w2.z = W_eb[(32 + 4 * q + 2) * EH + j];
            w2.w = W_eb[(32 + 4 * q + 3) * EH + j];
            sWh[q * 32 + j] = w2;
        }
    }
    if (!L0) {
        const float4* p = (const float4*)(ein + (size_t)e0b * 32);
        for (int idx = tid; idx < 64 * 8; idx += 256) {
            int e = idx >> 3, q = idx & 7;
            *(float4*)&sv[e * 36 + 4 * q] = p[idx];
        }
    }
    if (HE) {
        const float4* p = (const float4*)(he + (size_t)e0b * 32);
        for (int idx = tid; idx < 64 * 8; idx += 256) {
            int e = idx >> 3, q = idx & 7;
            *(float4*)&svh[e * 36 + 4 * q] = p[idx];
        }
    }
    __syncthreads();
    if (L0 && !fast) {
        for (int idx = tid; idx < 64 * 32; idx += 256) {
            int e = idx >> 5, k = idx & 31;
            sv[e * 36 + k] = fmaxf(sa[e] * swee[k] + sbee[k], 0.f);
        }
    }
    if (L0) __syncthreads();

    int lane = tid & 31, wid = tid >> 5;
    float gce = d_gce[lane];
    float pp = 0.f, pm = 0.f;
    if (L0) { pp = d_Pp[lane]; pm = d_Pm[lane]; }
    float esum = 0.f;
#pragma unroll
    for (int i = 0; i < 8; i++) {
        int el = wid * 8 + i;
        size_t e = e0b + el;
        int s = sidx[el], r = sidx[64 + el];
        float b = gce;
        if (L0 && fast) {
            float a = sa[el];
            b += (a >= 0.f) ? a * pp : -a * pm;
        } else {
#pragma unroll
            for (int q = 0; q < 8; q++)
                b += dot4(*(const float4*)&sv[el * 36 + 4 * q], sWe[q * 32 + lane]);
        }
        if (HE) {
#pragma unroll
            for (int q = 0; q < 8; q++)
                b += dot4(*(const float4*)&svh[el * 36 + 4 * q], sWh[q * 32 + lane]);
        }
        b += nsf[(size_t)s * 64 + lane] + nsf[(size_t)r * 64 + 32 + lane];
        float en = fmaxf(b, 0.f);
        if (EOUT) eout[e * 32 + lane] = en;
        atomicAdd(&accbuf[(size_t)s * 64 + lane], en);
        atomicAdd(&accbuf[(size_t)r * 64 + 32 + lane], en);
        if (SUM) esum += en;
    }
    if (SUM) {
        sred[tid] = esum;
        __syncthreads();
        if (wid == 0) {
            float s2 = 0.f;
#pragma unroll
            for (int w = 0; w < 8; w++) s2 += sred[w * 32 + lane];
            atomicAdd(&d_esum[lane], s2);
        }
    }
}

// ---------------- fused node step (r14 geometry + prefetch + smem-sourced td) ----------------
template <bool HASH, bool TD, bool SD, bool NSH, bool GLOB>
__global__ __launch_bounds__(256) void k_node16(
    const float* __restrict__ ndx_t, const float* __restrict__ hx,
    const float* __restrict__ accb, const float* __restrict__ W_nb,
    float* __restrict__ xsout, float* __restrict__ tdout, float* __restrict__ sdout,
    const float* __restrict__ degw, const float* __restrict__ coeff,
    const float* __restrict__ nsx1, const float* __restrict__ W_eb,
    float* __restrict__ nsf, float* __restrict__ accz,
    const float* __restrict__ W_gb, const float* __restrict__ b_gb,
    const float* __restrict__ b_eb, const float* __restrict__ b_nb,
    int save) {
    constexpr int KW = HASH ? 132 : 68;
    constexpr int KQ = HASH ? 32 : 16;
    extern __shared__ float sm[];
    float4* sW4 = (float4*)sm;
    float*  sx  = sm + 4096;
    float*  sv  = sm + (HASH ? 8192 : 4096);
    float4* nW4 = (float4*)sm;
    __shared__ int slast;
    int tid = threadIdx.x;
    int base = blockIdx.x * 32;
    // ---- prefetch epilogue operands early (hide LDG latency under GEMM) ----
    float4 ndpre[2];
    float dgpre[2];
#pragma unroll
    for (int rep = 0; rep < 2; rep++) {
        int idx = rep * 256 + tid;
        int n = idx >> 4, q = idx & 15;
        ndpre[rep] = ((const float4*)ndx_t)[(size_t)(base + n) * 16 + q];
        dgpre[rep] = SD ? degw[base + n] : 0.f;
    }
    for (int idx = tid; idx < KQ * 64; idx += 256) {
        int kq = idx >> 6, j = idx & 63;
        int r0 = (HASH ? 64 : 128) + 4 * kq;
        float4 w;
        w.x = W_nb[(r0 + 0) * NH + j];
        w.y = W_nb[(r0 + 1) * NH + j];
        w.z = W_nb[(r0 + 2) * NH + j];
        w.w = W_nb[(r0 + 3) * NH + j];
        sW4[idx] = w;
    }
    const float4* h4 = (const float4*)hx;
    const float4* a4 = (const float4*)accb;
    for (int idx = tid; idx < 32 * (HASH ? 32 : 16); idx += 256) {
        int n, q;
        if (HASH) { n = idx >> 5; q = idx & 31; }
        else      { n = idx >> 4; q = idx & 15; }
        float4 v;
        if (HASH) v = (q < 16) ? h4[(size_t)(base + n) * 16 + q]
                               : a4[(size_t)(base + n) * 16 + q - 16];
        else      v = a4[(size_t)(base + n) * 16 + q];
        *(float4*)&sv[n * KW + 4 * q] = v;
    }
    __syncthreads();
    int og = tid & 15, ng = tid >> 4;
    float acc[8];
#pragma unroll
    for (int i = 0; i < 8; i++) acc[i] = 0.f;
#pragma unroll 8
    for (int kq = 0; kq < KQ; kq++) {
        float4 v[2], w[4];
        v[0] = *(const float4*)&sv[ng * KW + 4 * kq];
        v[1] = *(const float4*)&sv[(ng + 16) * KW + 4 * kq];
#pragma unroll
        for (int d = 0; d < 4; d++) w[d] = sW4[kq * 64 + og + 16 * d];
#pragma unroll
        for (int c = 0; c < 2; c++)
#pragma unroll
            for (int d = 0; d < 4; d++) acc[c * 4 + d] += dot4(v[c], w[d]);
    }
    __syncthreads();   // GEMM reads done; safe to overwrite sx (weight region). sv stays live.
#pragma unroll
    for (int c = 0; c < 2; c++)
#pragma unroll
        for (int d = 0; d < 4; d++)
            sx[(ng + 16 * c) * 68 + og + 16 * d] = acc[c * 4 + d];
    if (NSH) {
        for (int idx = tid; idx < 16 * 64; idx += 256) {
            int kq = idx >> 6, j = idx & 63;
            int b0 = (j < 32) ? 128 : 256;
            int jj = j & 31;
            float4 w;
            w.x = W_eb[(b0 + 4 * kq + 0) * EH + jj];
            w.y = W_eb[(b0 + 4 * kq + 1) * EH + jj];
            w.z = W_eb[(b0 + 4 * kq + 2) * EH + jj];
            w.w = W_eb[(b0 + 4 * kq + 3) * EH + jj];
            nW4[idx] = w;
        }
    }
    __syncthreads();
    // vectorized epilogue: 2 reps, thread -> (node n, quad q); hx read from sv (HASH)
    float cw = SD ? coeff[0] : 0.f;
#pragma unroll
    for (int rep = 0; rep < 2; rep++) {
        int idx = rep * 256 + tid;
        int n = idx >> 4, q = idx & 15;
        size_t row = base + n;
        float4 a = *(const float4*)&sx[n * 68 + 4 * q];
        float4 nd = ndpre[rep];
        float4 g = *(const float4*)&d_gcn[4 * q];
        float4 x;
        x.x = fmaxf(a.x + nd.x + g.x, 0.f);
        x.y = fmaxf(a.y + nd.y + g.y, 0.f);
        x.z = fmaxf(a.z + nd.z + g.z, 0.f);
        x.w = fmaxf(a.w + nd.w + g.w, 0.f);
        *(float4*)&sx[n * 68 + 4 * q] = x;
        ((float4*)xsout)[row * 16 + q] = x;
        if (TD) {
            float4 t = x;
            if (HASH) {
                float4 h = *(const float4*)&sv[n * KW + 4 * q];   // hx staged in smem
                t.x -= h.x; t.y -= h.y; t.z -= h.z; t.w -= h.w;
            }
            ((float4*)tdout)[row * 16 + q] = t;
        }
        if (SD) {
            float dgv = -cw * dgpre[rep];
            ((float4*)sdout)[row * 16 + q] =
                make_float4(dgv * x.x, dgv * x.y, dgv * x.z, dgv * x.w);
        }
        if (NSH) ((float4*)accz)[row * 16 + q] = make_float4(0.f, 0.f, 0.f, 0.f);
    }
    if (NSH || GLOB) __syncthreads();
    if (GLOB && tid < 64) {
        float s = 0.f;
#pragma unroll
        for (int n = 0; n < 32; n++) s += sx[n * 68 + tid];
        atomicAdd(&d_xsum[tid], s);
    }
    if (NSH) {
        float a2[8];
#pragma unroll
        for (int i = 0; i < 8; i++) a2[i] = 0.f;
#pragma unroll
        for (int kq = 0; kq < 16; kq++) {
            float4 v[2], w[4];
            v[0] = *(const float4*)&sx[ng * 68 + 4 * kq];
            v[1] = *(const float4*)&sx[(ng + 16) * 68 + 4 * kq];
#pragma unroll
            for (int d = 0; d < 4; d++) w[d] = nW4[kq * 64 + og + 16 * d];
#pragma unroll
            for (int c = 0; c < 2; c++)
#pragma unroll
                for (int d = 0; d < 4; d++) a2[c * 4 + d] += dot4(v[c], w[d]);
        }
#pragma unroll
        for (int c = 0; c < 2; c++) {
            size_t row = base + ng + 16 * c;
#pragma unroll
            for (int d = 0; d < 4; d++) {
                int j = og + 16 * d;
                nsf[row * 64 + j] = a2[c * 4 + d] + nsx1[row * 64 + j];
            }
        }
    }
    if (GLOB) {
        __syncthreads();
        __threadfence();
        if (tid == 0) slast = (atomicAdd(&d_ctr, 1) == (int)gridDim.x - 1);
        __syncthreads();
        if (slast) {
            float* gcat = sx;
            float* gnew = sx + 160;
            if (tid < 64) gcat[tid] = d_xsum[tid] * (1.0f / N_C);
            else if (tid < 96) gcat[tid] = d_esum[tid - 64] * (1.0f / E_C);
            else if (tid < 160) gcat[tid] = d_g[tid - 96];
            __syncthreads();
            if (tid < GH) {
                float v = b_gb[tid];
                for (int k = 0; k < 160; k++) v += gcat[k] * W_gb[k * GH + tid];
                gnew[tid] = fmaxf(v, 0.f);
            }
            __syncthreads();
            if (tid < GH) {
                d_g[tid] = gnew[tid];
                if (save) d_gsave[tid] = gnew[tid];
                d_xsum[tid] = 0.f;
            }
            if (tid < EH) {
                d_esum[tid] = 0.f;
                float v = b_eb[tid];
#pragma unroll
                for (int k = 0; k < GH; k++) v += gnew[k] * W_eb[(320 + k) * EH + tid];
                d_gce[tid] = v;
            } else if (tid < 32 + NH) {
                int j = tid - 32;
                float v = b_nb[j];
#pragma unroll
                for (int k = 0; k < GH; k++) v += gnew[k] * W_nb[(192 + k) * NH + j];
                d_gcn[j] = v;
            }
            if (tid == 0) d_ctr = 0;
        }
    }
}

// ---------------- node-parallel sder over recv-CSR (all 4 steps) ----------------
__global__ __launch_bounds__(256) void k_sder8(const int* __restrict__ pr,
                                               const int2* __restrict__ pre,
                                               const float* __restrict__ spL,
                                               const float* __restrict__ coeff,
                                               const float* __restrict__ xsB,
                                               float* __restrict__ sd_out) {
    int lane = threadIdx.x & 31, wid = threadIdx.x >> 5;
    int n = blockIdx.x * 8 + wid;
    int p0 = pr[n], p1 = pr[n + 1];
    float a[8] = {0.f, 0.f, 0.f, 0.f, 0.f, 0.f, 0.f, 0.f};
    for (int i = p0; i < p1; i++) {
        int2 es = pre[i];
        float w = spL[es.x];
        const float* xr = xsB + (size_t)es.y * 64;
#pragma unroll
        for (int t = 0; t < 4; t++) {
            a[t * 2]     += w * xr[(size_t)t * N_C * 64 + lane];
            a[t * 2 + 1] += w * xr[(size_t)t * N_C * 64 + 32 + lane];
        }
    }
    float cw = coeff[0];
#pragma unroll
    for (int t = 0; t < 4; t++) {
        size_t o = (size_t)t * N_C * 64 + (size_t)n * 64;
        sd_out[o + lane]      += cw * a[t * 2];
        sd_out[o + 32 + lane] += cw * a[t * 2 + 1];
    }
}

// ---------------- decode: quad-major weights ----------------
__global__ __launch_bounds__(256) void k_decode13(const float* __restrict__ xa,
                                                  const float* __restrict__ xb,
                                                  const float* __restrict__ W1,
                                                  const float* __restrict__ b1,
                                                  const float* __restrict__ W2,
                                                  const float* __restrict__ b2,
                                                  float* __restrict__ outn) {
    __shared__ float4 sW4[16 * 64];
    __shared__ float sv[64 * 68];
    __shared__ float sw2[NH];
    int tid = threadIdx.x;
    int base = blockIdx.x * 64;
    for (int idx = tid; idx < 16 * 64; idx += 256) {
        int kq = idx >> 6, j = idx & 63;
        float4 w;
        w.x = W1[(4 * kq + 0) * NH + j];
        w.y = W1[(4 * kq + 1) * NH + j];
        w.z = W1[(4 * kq + 2) * NH + j];
        w.w = W1[(4 * kq + 3) * NH + j];
        sW4[idx] = w;
    }
    const float4* a4 = (const float4*)xa;
    const float4* b4 = (const float4*)xb;
    for (int idx = tid; idx < 64 * 16; idx += 256) {
        int n = idx >> 4, q = idx & 15;
        float4 va = a4[(size_t)(base + n) * 16 + q];
        float4 vb = b4[(size_t)(base + n) * 16 + q];
        va.x += vb.x; va.y += vb.y; va.z += vb.z; va.w += vb.w;
        *(float4*)&sv[n * 68 + 4 * q] = va;
    }
    if (tid < NH) sw2[tid] = W2[tid];
    __syncthreads();
    int og = tid & 15, ng = tid >> 4;
    float acc[16];
#pragma unroll
    for (int i = 0; i < 16; i++) acc[i] = 0.f;
#pragma unroll
    for (int kq = 0; kq < 16; kq++) {
        float4 v[4], w[4];
#pragma unroll
        for (int c = 0; c < 4; c++) v[c] = *(const float4*)&sv[(ng + 16 * c) * 68 + 4 * kq];
#pragma unroll
        for (int d = 0; d < 4; d++) w[d] = sW4[kq * 64 + og + 16 * d];
#pragma unroll
        for (int c = 0; c < 4; c++)
#pragma unroll
            for (int d = 0; d < 4; d++) acc[c * 4 + d] += dot4(v[c], w[d]);
    }
    float w2[4], bb[4];
#pragma unroll
    for (int d = 0; d < 4; d++) { w2[d] = sw2[og + 16 * d]; bb[d] = b1[og + 16 * d]; }
    float b20 = b2[0];
#pragma unroll
    for (int c = 0; c < 4; c++) {
        float p = 0.f;
#pragma unroll
        for (int d = 0; d < 4; d++) p += fmaxf(acc[c * 4 + d] + bb[d], 0.f) * w2[d];
        p += __shfl_down_sync(0xffffffffu, p, 8);
        p += __shfl_down_sync(0xffffffffu, p, 4);
        p += __shfl_down_sync(0xffffffffu, p, 2);
        p += __shfl_down_sync(0xffffffffu, p, 1);
        if (og == 0) outn[base + ng + 16 * c] = p + b20;
    }
}

// ---------------- host launcher ----------------
extern "C" void kernel_launch(void* const* d_in, const int* in_sizes, int n_in,
                              void* d_out, int out_size) {
    const float* node_attr  = (const float*)d_in[0];
    const float* edge_attr  = (const float*)d_in[1];
    const int*   edge_index = (const int*)  d_in[2];
    const float* spL        = (const float*)d_in[3];
    const float* gattr      = (const float*)d_in[4];
    const float* coeff      = (const float*)d_in[5];
    const float* W_ee = (const float*)d_in[6];
    const float* b_ee = (const float*)d_in[7];
    const float* W_ne = (const float*)d_in[8];
    const float* b_ne = (const float*)d_in[9];
    const float* W_eb = (const float*)d_in[10];
    const float* b_eb = (const float*)d_in[11];
    const float* W_nb = (const float*)d_in[12];
    const float* b_nb = (const float*)d_in[13];
    const float* W_gb = (const float*)d_in[14];
    const float* b_gb = (const float*)d_in[15];
    const float* W_nd1 = (const float*)d_in[16];
    const float* b_nd1 = (const float*)d_in[17];
    const float* W_nd2 = (const float*)d_in[18];
    const float* b_nd2 = (const float*)d_in[19];

    float* out    = (float*)d_out;
    float* out_td = out + (size_t)T_C * N_C;
    float* out_sd = out_td + (size_t)T_C * N_C * NH;

    float *xenc, *xsA, *xsB, *nsx, *ndx, *nsf, *acc, *es0, *e1;
    float *degw, *gsave;
    int *ptr_r;
    int2 *csr_r_es;
    cudaGetSymbolAddress((void**)&xenc, d_xenc);
    cudaGetSymbolAddress((void**)&xsA,  d_xsA);
    cudaGetSymbolAddress((void**)&xsB,  d_xsB);
    cudaGetSymbolAddress((void**)&nsx,  d_nsx);
    cudaGetSymbolAddress((void**)&ndx,  d_ndx);
    cudaGetSymbolAddress((void**)&nsf,  d_nsf);
    cudaGetSymbolAddress((void**)&acc,  d_acc);
    cudaGetSymbolAddress((void**)&es0,  d_es0);
    cudaGetSymbolAddress((void**)&e1,   d_e1);
    cudaGetSymbolAddress((void**)&degw, d_degw);
    cudaGetSymbolAddress((void**)&gsave, d_gsave);
    cudaGetSymbolAddress((void**)&ptr_r, d_ptr_r);
    cudaGetSymbolAddress((void**)&csr_r_es, d_csr_r_es);

    const int SM_H = (8192 + 32 * 132) * 4;   // 49664
    const int SM_L = (4096 + 32 * 68) * 4;    // 25088
    cudaFuncSetAttribute(k_node16<false, false, false, true,  true >, cudaFuncAttributeMaxDynamicSharedMemorySize, SM_L);
    cudaFuncSetAttribute(k_node16<true,  false, false, true,  true >, cudaFuncAttributeMaxDynamicSharedMemorySize, SM_H);
    cudaFuncSetAttribute(k_node16<true,  false, false, false, false>, cudaFuncAttributeMaxDynamicSharedMemorySize, SM_H);
    cudaFuncSetAttribute(k_node16<false, true,  true,  true,  true >, cudaFuncAttributeMaxDynamicSharedMemorySize, SM_L);
    cudaFuncSetAttribute(k_node16<true,  true,  true,  true,  true >, cudaFuncAttributeMaxDynamicSharedMemorySize, SM_H);
    cudaFuncSetAttribute(k_node16<true,  true,  true,  false, false>, cudaFuncAttributeMaxDynamicSharedMemorySize, SM_H);

    const int EGRID = E_C / 64;      // 5000
    const int NGRID = N_C / 32;      // 625
    const size_t NSZ = (size_t)N_C * NH;
    const size_t ESZ = (size_t)E_C * EH;

    // 1. encode (zeros CSR counters / degw / ctr)
    k_encode<<<(T_C * N_C) / 4, 256>>>(node_attr, W_ne, b_ne, xenc);
    // 2. batch_pre L0 (+prep, +ginit from gattr, +nsf/acc init)
    k_batch_pre<false, true><<<(T_C * N_C) / 32, 256>>>(xenc, nullptr, W_eb, W_nb,
        nsx, ndx, nsf, acc, gattr, b_eb, b_nb, W_ee, b_ee);
    // 3. L0 edge t=0
    k_edge10<true, false, true, true><<<EGRID, 256>>>(edge_index, edge_attr, nullptr, nullptr,
        es0, nsf, acc, W_eb, W_ee, b_ee);
    // 4. L0 node t=0  <-- ncu capture window
    k_node16<false, false, false, true, true><<<NGRID, 256, SM_L>>>(
        ndx, nullptr, acc, W_nb, xsA, nullptr, nullptr, nullptr, nullptr,
        nsx + NSZ, W_eb, nsf, acc, W_gb, b_gb, b_eb, b_nb, 1);
    // 5-7. recv CSR build (needed only by sder at the end)
    k_hist_r<<<E_C / 256, 256>>>(edge_index, spL);
    k_scan_r<<<1, 256>>>();
    k_scatter_r<<<E_C / 256, 256>>>(edge_index);

    // ================= layer 0, t=1..3 =================
    for (int t = 1; t < T_C; t++) {
        const float* ea_t = edge_attr + (size_t)t * E_C;
        float* es_t = es0 + (size_t)t * ESZ;
        if (t < 3)
            k_edge10<true, true, true, true><<<EGRID, 256>>>(edge_index, ea_t, nullptr,
                es0 + (size_t)(t - 1) * ESZ, es_t, nsf, acc, W_eb, W_ee, b_ee);
        else
            k_edge10<true, true, false, true><<<EGRID, 256>>>(edge_index, ea_t, nullptr,
                es0 + (size_t)(t - 1) * ESZ, es_t, nsf, acc, W_eb, W_ee, b_ee);
        float* xs_t = xsA + (size_t)t * NSZ;
        const float* nsx1 = nsx + (size_t)(t + 1) * NSZ;
        if (t < 3)
            k_node16<true, false, false, true, true><<<NGRID, 256, SM_H>>>(
                ndx + (size_t)t * NSZ, xsA + (size_t)(t - 1) * NSZ, acc, W_nb, xs_t, nullptr, nullptr, nullptr, nullptr,
                nsx1, W_eb, nsf, acc, W_gb, b_gb, b_eb, b_nb, 0);
        else
            k_node16<true, false, false, false, false><<<NGRID, 256, SM_H>>>(
                ndx + (size_t)t * NSZ, xsA + (size_t)(t - 1) * NSZ, acc, W_nb, xs_t, nullptr, nullptr, nullptr, nullptr,
                nullptr, W_eb, nsf, acc, W_gb, b_gb, b_eb, b_nb, 0);
    }

    // ================= layer 1 =================
    k_batch_pre<true, false><<<(T_C * N_C) / 32, 256>>>(xsA, xenc, W_eb, W_nb,
        nsx, ndx, nsf, acc, gsave, b_eb, b_nb, W_ee, b_ee);
    for (int t = 0; t < T_C; t++) {
        const float* es_t = es0 + (size_t)t * ESZ;
        if (t == 0)
            k_edge10<false, false, true, true><<<EGRID, 256>>>(edge_index, nullptr, es_t,
                nullptr, e1, nsf, acc, W_eb, W_ee, b_ee);
        else if (t < 3)
            k_edge10<false, true, true, true><<<EGRID, 256>>>(edge_index, nullptr, es_t,
                e1, e1, nsf, acc, W_eb, W_ee, b_ee);
        else
            k_edge10<false, true, false, false><<<EGRID, 256>>>(edge_index, nullptr, es_t,
                e1, e1, nsf, acc, W_eb, W_ee, b_ee);
        float* xs_t = xsB + (size_t)t * NSZ;
        float* td_t = out_td + (size_t)t * NSZ;
        float* sd_t = out_sd + (size_t)t * NSZ;
        const float* nsx1 = nsx + (size_t)(t + 1) * NSZ;
        if (t == 0)
            k_node16<false, true, true, true, true><<<NGRID, 256, SM_L>>>(
                ndx + (size_t)t * NSZ, nullptr, acc, W_nb, xs_t, td_t, sd_t, degw, coeff,
                nsx1, W_eb, nsf, acc, W_gb, b_gb, b_eb, b_nb, 0);
        else if (t < 3)
            k_node16<true, true, true, true, true><<<NGRID, 256, SM_H>>>(
                ndx + (size_t)t * NSZ, xsB + (size_t)(t - 1) * NSZ, acc, W_nb, xs_t, td_t, sd_t, degw, coeff,
                nsx1, W_eb, nsf, acc, W_gb, b_gb, b_eb, b_nb, 0);
        else
            k_node16<true, true, true, false, false><<<NGRID, 256, SM_H>>>(
                ndx + (size_t)t * NSZ, xsB + (size_t)(t - 1) * NSZ, acc, W_nb, xs_t, td_t, sd_t, degw, coeff,
                nullptr, W_eb, nsf, acc, W_gb, b_gb, b_eb, b_nb, 0);
    }

    k_sder8<<<N_C / 8, 256>>>(ptr_r, csr_r_es, spL, coeff, xsB, out_sd);
    k_decode13<<<(T_C * N_C) / 64, 256>>>(xsA, xsB, W_nd1, b_nd1, W_nd2, b_nd2, out);
}